// round 1
// baseline (speedup 1.0000x reference)
#include <cuda_runtime.h>
#include <math.h>

#define T_LEN  2048
#define DM     1024
#define HQ     16
#define HD     64          // head dim D
#define NB     32          // number of key blocks
#define BS     64          // block size
#define SSEL   16          // selected blocks per token
#define NPROJ  1200        // 1024 q + 64 k + 64 v + 48 g
#define KOFF   1024
#define VOFF   1088
#define GOFF   1152
#define NEGF   -1e30f

// ---------------- device scratch (no runtime allocation allowed) ----------------
__device__ float d_Wall[NPROJ * DM];        // ~4.9 MB
__device__ float d_qkvg[T_LEN * NPROJ];     // ~9.8 MB
__device__ float d_kc[NB * HD];
__device__ float d_vc[NB * HD];
__device__ float d_omix[T_LEN * HQ * HD];   // 8 MB
__device__ int   d_blk[T_LEN * SSEL];

// ---------------- weight concat: Wall = [Wq; Wk; Wv; Wg] ----------------
__global__ void concat_w_kernel(const float* __restrict__ Wq, const float* __restrict__ Wk,
                                const float* __restrict__ Wv, const float* __restrict__ Wg) {
    int i = blockIdx.x * blockDim.x + threadIdx.x;
    if (i >= NPROJ * DM) return;
    int r = i / DM, c = i % DM;
    float v;
    if (r < 1024)       v = Wq[r * DM + c];
    else if (r < 1088)  v = Wk[(r - 1024) * DM + c];
    else if (r < 1152)  v = Wv[(r - 1088) * DM + c];
    else                v = Wg[(r - 1152) * DM + c];
    d_Wall[i] = v;
}

// ---------------- fp32 SGEMM: C[M,N] = A[M,K] * B[N,K]^T ----------------
// 128x128 tile, K-tile 8, 256 threads, 8x8 per thread.
#define BM 128
#define BN 128
#define BK 8
__global__ __launch_bounds__(256) void gemm_tn_kernel(
    const float* __restrict__ A, const float* __restrict__ B, float* __restrict__ C,
    int M, int N, int K, int ldc) {
    __shared__ float As[BK][BM];
    __shared__ float Bs[BK][BN];
    const int bm = blockIdx.y * BM;
    const int bn = blockIdx.x * BN;
    const int tid = threadIdx.x;
    const int trow = tid >> 4;      // 0..15
    const int tcol = tid & 15;      // 0..15
    const int lr = tid >> 1;        // 0..127
    const int lk = (tid & 1) * 4;   // 0 or 4

    float acc[8][8];
#pragma unroll
    for (int i = 0; i < 8; i++)
#pragma unroll
        for (int j = 0; j < 8; j++) acc[i][j] = 0.f;

    const float* Aptr = A + (size_t)(bm + lr) * K + lk;
    const float* Bptr = B + (size_t)(bn + lr) * K + lk;
    const bool bvalid = (bn + lr) < N;

    for (int k0 = 0; k0 < K; k0 += BK) {
        float4 a = *reinterpret_cast<const float4*>(Aptr + k0);
        float4 b = bvalid ? *reinterpret_cast<const float4*>(Bptr + k0)
                          : make_float4(0.f, 0.f, 0.f, 0.f);
        As[lk + 0][lr] = a.x; As[lk + 1][lr] = a.y; As[lk + 2][lr] = a.z; As[lk + 3][lr] = a.w;
        Bs[lk + 0][lr] = b.x; Bs[lk + 1][lr] = b.y; Bs[lk + 2][lr] = b.z; Bs[lk + 3][lr] = b.w;
        __syncthreads();
#pragma unroll
        for (int kk = 0; kk < BK; kk++) {
            float4 a0 = *reinterpret_cast<const float4*>(&As[kk][trow * 8]);
            float4 a1 = *reinterpret_cast<const float4*>(&As[kk][trow * 8 + 4]);
            float4 b0 = *reinterpret_cast<const float4*>(&Bs[kk][tcol * 8]);
            float4 b1 = *reinterpret_cast<const float4*>(&Bs[kk][tcol * 8 + 4]);
            float av[8] = {a0.x, a0.y, a0.z, a0.w, a1.x, a1.y, a1.z, a1.w};
            float bv[8] = {b0.x, b0.y, b0.z, b0.w, b1.x, b1.y, b1.z, b1.w};
#pragma unroll
            for (int i = 0; i < 8; i++)
#pragma unroll
                for (int j = 0; j < 8; j++) acc[i][j] = fmaf(av[i], bv[j], acc[i][j]);
        }
        __syncthreads();
    }
#pragma unroll
    for (int i = 0; i < 8; i++) {
        int r = bm + trow * 8 + i;
#pragma unroll
        for (int j = 0; j < 8; j++) {
            int c = bn + tcol * 8 + j;
            if (c < N) C[(size_t)r * ldc + c] = acc[i][j];
        }
    }
}

// ---------------- block mean pooling for k_c / v_c ----------------
__global__ void meanpool_kernel() {
    int i = blockIdx.x * blockDim.x + threadIdx.x;
    if (i >= 2 * NB * HD) return;
    int which = (i >= NB * HD);
    int e = i & (NB * HD - 1);
    int c = e >> 6, d = e & 63;
    int off = which ? VOFF : KOFF;
    float s = 0.f;
#pragma unroll 8
    for (int j = 0; j < BS; j++)
        s += d_qkvg[(size_t)(c * BS + j) * NPROJ + off + d];
    s *= (1.f / BS);
    if (which) d_vc[e] = s; else d_kc[e] = s;
}

// ---------------- compressed attention + top-k selection (one CTA per token) -------
#define QSL 66   // padded head-row stride (bank-conflict free for head-strided reads)
#define KCL 68   // padded kc/vc row stride (float4-aligned)
#define SPL 34   // padded score-row stride
__global__ __launch_bounds__(256) void cmp_attn_kernel() {
    const int t = blockIdx.x;
    const int tid = threadIdx.x;
    __shared__ float qs[HQ * QSL];
    __shared__ float kcs[NB * KCL];
    __shared__ float vcs[NB * KCL];
    __shared__ float sp[HQ * SPL];
    __shared__ float imp[NB];
    __shared__ float linv[HQ];

    const float* row = d_qkvg + (size_t)t * NPROJ;
    for (int e = tid; e < HQ * HD; e += 256)
        qs[(e >> 6) * QSL + (e & 63)] = row[e];
    for (int e = tid; e < NB * HD; e += 256) {
        int c = e >> 6, d = e & 63;
        kcs[c * KCL + d] = d_kc[e];
        vcs[c * KCL + d] = d_vc[e];
    }
    __syncthreads();

    const int nvis = (t + 1) >> 6;   // fully-past blocks

    // scores: thread -> (h = tid&15, c = tid>>4 .. +2 strided)
    for (int e = tid; e < HQ * NB; e += 256) {
        int h = e & 15, c = e >> 4;
        float sv = NEGF;
        if (c < nvis) {
            float a = 0.f;
#pragma unroll 16
            for (int d = 0; d < HD; d++)
                a = fmaf(qs[h * QSL + d], kcs[c * KCL + d], a);
            sv = a * 0.125f;
        }
        sp[h * SPL + c] = sv;
    }
    __syncthreads();

    // per-head softmax (unnormalized exp + 1/l)
    if (tid < HQ) {
        int h = tid;
        float m = NEGF;
        for (int c = 0; c < nvis; c++) m = fmaxf(m, sp[h * SPL + c]);
        float l = 0.f;
        for (int c = 0; c < nvis; c++) {
            float p = __expf(sp[h * SPL + c] - m);
            sp[h * SPL + c] = p;
            l += p;
        }
        linv[h] = (nvis > 0) ? 1.f / l : 0.f;
    }
    __syncthreads();

    // normalize (and zero invisible)
    for (int e = tid; e < HQ * NB; e += 256) {
        int h = e & 15, c = e >> 4;
        sp[h * SPL + c] = (c < nvis) ? sp[h * SPL + c] * linv[h] : 0.f;
    }
    __syncthreads();

    // importance = sum over heads
    if (tid < NB) {
        float s = 0.f;
#pragma unroll
        for (int h = 0; h < HQ; h++) s += sp[h * SPL + tid];
        imp[tid] = s;
    }
    // o_cmp: thread -> (h = tid>>4, d0 = (tid&15)*4)
    {
        int h = tid >> 4;
        int d0 = (tid & 15) * 4;
        float4 o = make_float4(0.f, 0.f, 0.f, 0.f);
        for (int c = 0; c < nvis; c++) {
            float p = sp[h * SPL + c];
            float4 vv = *reinterpret_cast<const float4*>(&vcs[c * KCL + d0]);
            o.x = fmaf(p, vv.x, o.x); o.y = fmaf(p, vv.y, o.y);
            o.z = fmaf(p, vv.z, o.z); o.w = fmaf(p, vv.w, o.w);
        }
        float gx = row[GOFF + h * 3 + 0];
        float gcmp = 1.f / (1.f + __expf(-gx));
        o.x *= gcmp; o.y *= gcmp; o.z *= gcmp; o.w *= gcmp;
        *reinterpret_cast<float4*>(&d_omix[(size_t)t * (HQ * HD) + h * HD + d0]) = o;
    }
    __syncthreads();

    // top-16 selection (value desc, tie-break lowest index == jax.lax.top_k)
    if (tid == 0) {
        const int cur = t >> 6;
        float v[NB];
#pragma unroll
        for (int c = 0; c < NB; c++) v[c] = (c <= cur) ? imp[c] : NEGF;
        v[0] = INFINITY;
        v[cur] = INFINITY;
        for (int s = 0; s < SSEL; s++) {
            float best = -INFINITY; int bi = 0;
#pragma unroll
            for (int c = 0; c < NB; c++)
                if (v[c] > best) { best = v[c]; bi = c; }
            d_blk[t * SSEL + s] = bi;
            v[bi] = -INFINITY;
        }
    }
}

// ---------------- selected block-sparse attention (one CTA per token) -------------
#define KVL 68  // padded kv row stride (float4-aligned, conflict-free)
__global__ __launch_bounds__(256) void slc_attn_kernel() {
    const int t = blockIdx.x;
    const int tid = threadIdx.x;
    __shared__ float qs[HQ * QSL];
    __shared__ float kv[BS * KVL];
    __shared__ float sp[HQ * QSL];      // 16 x 64 scores, stride 66
    __shared__ float mh[HQ], alpha_s[HQ], lh[HQ];
    __shared__ int blks[SSEL];

    const float* row = d_qkvg + (size_t)t * NPROJ;
    for (int e = tid; e < HQ * HD; e += 256)
        qs[(e >> 6) * QSL + (e & 63)] = row[e];
    if (tid < SSEL) blks[tid] = d_blk[t * SSEL + tid];
    if (tid < HQ) { mh[tid] = NEGF; lh[tid] = 0.f; }
    __syncthreads();

    const int h_o = tid >> 4;           // pv-phase head
    const int d0  = (tid & 15) * 4;     // pv-phase dim base
    const int hs  = tid & 15;           // score-phase head
    const int jb  = (tid >> 4) * 4;     // score-phase j base
    float4 oacc = make_float4(0.f, 0.f, 0.f, 0.f);

    for (int b = 0; b < SSEL; b++) {
        const int base = blks[b] * BS;

        // load K block (64 x 64 f32) into kv
        for (int e = tid; e < BS * (HD / 4); e += 256) {
            int j = e >> 4, c4 = (e & 15) * 4;
            *reinterpret_cast<float4*>(&kv[j * KVL + c4]) =
                *reinterpret_cast<const float4*>(&d_qkvg[(size_t)(base + j) * NPROJ + KOFF + c4]);
        }
        __syncthreads();

        // scores: each thread 4 dots of length 64
#pragma unroll
        for (int jj = 0; jj < 4; jj++) {
            int j = jb + jj;
            int tok = base + j;
            float a = 0.f;
#pragma unroll 16
            for (int d = 0; d < HD; d++)
                a = fmaf(qs[hs * QSL + d], kv[j * KVL + d], a);
            sp[hs * QSL + j] = (tok <= t) ? a * 0.125f : NEGF;
        }
        __syncthreads();

        // per-head running max + alpha
        if (tid < HQ) {
            float m = NEGF;
            for (int j = 0; j < BS; j++) m = fmaxf(m, sp[tid * QSL + j]);
            float mn = fmaxf(mh[tid], m);
            alpha_s[tid] = __expf(mh[tid] - mn);  // NEGF-NEGF -> exp(0)=1, l==0 so harmless
            mh[tid] = mn;
        }
        __syncthreads();

        // exponentiate + load V block (disjoint smem, concurrent)
        {
            float mn = mh[hs];
#pragma unroll
            for (int jj = 0; jj < 4; jj++) {
                int j = jb + jj;
                float s = sp[hs * QSL + j];
                sp[hs * QSL + j] = (s <= NEGF) ? 0.f : __expf(s - mn);
            }
        }
        for (int e = tid; e < BS * (HD / 4); e += 256) {
            int j = e >> 4, c4 = (e & 15) * 4;
            *reinterpret_cast<float4*>(&kv[j * KVL + c4]) =
                *reinterpret_cast<const float4*>(&d_qkvg[(size_t)(base + j) * NPROJ + VOFF + c4]);
        }
        __syncthreads();

        // l update + P@V accumulate
        if (tid < HQ) {
            float l = 0.f;
            for (int j = 0; j < BS; j++) l += sp[tid * QSL + j];
            lh[tid] = lh[tid] * alpha_s[tid] + l;
        }
        {
            float al = alpha_s[h_o];
            oacc.x *= al; oacc.y *= al; oacc.z *= al; oacc.w *= al;
#pragma unroll 8
            for (int j = 0; j < BS; j++) {
                float p = sp[h_o * QSL + j];
                float4 vv = *reinterpret_cast<const float4*>(&kv[j * KVL + d0]);
                oacc.x = fmaf(p, vv.x, oacc.x); oacc.y = fmaf(p, vv.y, oacc.y);
                oacc.z = fmaf(p, vv.z, oacc.z); oacc.w = fmaf(p, vv.w, oacc.w);
            }
        }
        __syncthreads();
    }

    // finalize: o_mix += g_slc * o_slc / l
    float li = 1.f / lh[h_o];
    float gx = row[GOFF + h_o * 3 + 1];
    float gslc = 1.f / (1.f + __expf(-gx));
    float* op = &d_omix[(size_t)t * (HQ * HD) + h_o * HD + d0];
    float4 prev = *reinterpret_cast<float4*>(op);
    prev.x += gslc * oacc.x * li;
    prev.y += gslc * oacc.y * li;
    prev.z += gslc * oacc.z * li;
    prev.w += gslc * oacc.w * li;
    *reinterpret_cast<float4*>(op) = prev;
}

// ---------------- launch ----------------
extern "C" void kernel_launch(void* const* d_in, const int* in_sizes, int n_in,
                              void* d_out, int out_size) {
    const float* x  = (const float*)d_in[0];
    const float* Wq = (const float*)d_in[1];
    const float* Wk = (const float*)d_in[2];
    const float* Wv = (const float*)d_in[3];
    const float* Wg = (const float*)d_in[4];
    const float* Wo = (const float*)d_in[5];
    float* out = (float*)d_out;

    float *p_Wall, *p_qkvg, *p_omix;
    cudaGetSymbolAddress((void**)&p_Wall, d_Wall);
    cudaGetSymbolAddress((void**)&p_qkvg, d_qkvg);
    cudaGetSymbolAddress((void**)&p_omix, d_omix);

    // 1. concat projection weights
    concat_w_kernel<<<(NPROJ * DM) / 256, 256>>>(Wq, Wk, Wv, Wg);
    // 2. fused q/k/v/g projection: [2048,1200] = x @ Wall^T
    gemm_tn_kernel<<<dim3((NPROJ + BN - 1) / BN, T_LEN / BM), 256>>>(
        x, p_Wall, p_qkvg, T_LEN, NPROJ, DM, NPROJ);
    // 3. block mean pooling
    meanpool_kernel<<<(2 * NB * HD) / 256, 256>>>();
    // 4. compressed attention + top-k selection
    cmp_attn_kernel<<<T_LEN, 256>>>();
    // 5. selected block-sparse attention
    slc_attn_kernel<<<T_LEN, 256>>>();
    // 6. output projection: out[2048,1024] = o_mix @ Wo^T
    gemm_tn_kernel<<<dim3(DM / BN, T_LEN / BM), 256>>>(
        p_omix, Wo, out, T_LEN, DM, DM, DM);
}